// round 6
// baseline (speedup 1.0000x reference)
#include <cuda_runtime.h>
#include <math.h>
#include <cstdint>

#define FULL_MASK 0xFFFFFFFFu
typedef unsigned long long ull;

__device__ __forceinline__ ull pk2(float lo, float hi) {
    ull r; asm("mov.b64 %0, {%1, %2};" : "=l"(r) : "f"(lo), "f"(hi)); return r;
}
__device__ __forceinline__ void fma2(ull& d, ull a, ull b) {
    asm("fma.rn.f32x2 %0, %1, %2, %0;" : "+l"(d) : "l"(a), "l"(b));
}
__device__ __forceinline__ void unpk(ull v, float& a, float& b) {
    asm("mov.b64 {%0, %1}, %2;" : "=f"(a), "=f"(b) : "l"(v));
}

// bs=65536, S=10, D=100, H=16, 5 greedy steps.
// s-per-lane mapping: warp handles 3 batches; lane = (b3 = l/10, s = l%10), lanes 30/31 shadow.
// Each lane computes ALL 16 h for its row -> corpus value loaded once, reused 16x in registers.
// NO shared memory: corpus via per-lane LDG.128 (row-contiguous), weights via warp-uniform
// L1-hot LDG.128, ic/nic/src/sum in registers, argmax + row-broadcast via shfl.
//
// FROZEN numerics contract (rel_err 9.3e-8 in R4/R5):
//   - every dot: single-accumulator sequential-k fmaf chain (ascending), bias AFTER
//   - f32x2 pairs two INDEPENDENT h-chains (lo/hi rounded separately => bit-identical)
//   - src = mean(ui): append-order sum; /2,/4 as exact *0.5/*0.25; /3,/5 via __fdiv_rn
//   - softmax skipped (monotone); first-index argmax via strict >
__global__ __launch_bounds__(128, 4)
void attn_greedy_kernel(const float* __restrict__ g_ui,     // [bs,16]
                        const float* __restrict__ g_corp,   // [bs,10,100]
                        const float* __restrict__ g_wp,     // [100,16]
                        const float* __restrict__ g_bp,     // [16]
                        const float* __restrict__ g_wk,     // [16,16]
                        const float* __restrict__ g_bk,     // [16]
                        float* __restrict__ g_out,          // [bs,6,16]
                        int n_batch)
{
    const int tid  = threadIdx.x;
    const int w    = tid >> 5;
    const int lane = tid & 31;
    const int l    = (lane < 30) ? lane : (lane - 30);   // lanes 30,31 shadow lanes 0,1
    const int b3   = l / 10;                             // batch-in-triple 0..2
    const int s    = l - b3 * 10;                        // row 0..9
    const int grp  = b3 * 10;                            // group base lane
    const bool writer = (lane < 30);

    const int warp_id  = (blockIdx.x << 2) + w;
    const int n_warps  = gridDim.x << 2;
    const int n_triple = (n_batch + 2) / 3;

    for (int tr = warp_id; tr < n_triple; tr += n_warps) {
        const int  b     = tr * 3 + b3;
        const bool valid = writer && (b < n_batch);
        const int  bl    = (b < n_batch) ? b : (n_batch - 1);   // clamped for loads

        // ---- ui: every lane of a group holds the full 16-vector ----
        float sum[16], src[16];
        {
            const float4* u4 = (const float4*)(g_ui + (size_t)bl * 16);
            #pragma unroll
            for (int i = 0; i < 4; i++) {
                float4 v = u4[i];
                sum[4*i]=v.x; sum[4*i+1]=v.y; sum[4*i+2]=v.z; sum[4*i+3]=v.w;
            }
            #pragma unroll
            for (int h = 0; h < 16; h++) src[h] = sum[h];    // mean of 1 vector
        }
        if (valid) {
            float* o = g_out + (size_t)b * 96;
            o[s] = sum[s];
            if (s < 6) o[10 + s] = sum[10 + s];
        }

        // ---- projection: ic[h] = seq-fma_{d=0..99} corp[s,d]*Wp[d,h], then +bp ----
        // f32x2 accumulators: pair p holds chains (2p, 2p+1).
        ull icp[8];
        #pragma unroll
        for (int p = 0; p < 8; p++) icp[p] = 0ull;
        const float* crow = g_corp + (size_t)bl * 1000 + s * 100;   // 16B-aligned (s*400B)
        #pragma unroll 5
        for (int c = 0; c < 25; c++) {
            float4 cv = *(const float4*)(crow + 4 * c);             // d = 4c..4c+3
            #pragma unroll
            for (int q = 0; q < 4; q++) {                           // d ascending
                float cd = (q == 0) ? cv.x : (q == 1) ? cv.y : (q == 2) ? cv.z : cv.w;
                ull cdd = pk2(cd, cd);
                const ulonglong2* wr = (const ulonglong2*)(g_wp + (4*c + q) * 16);  // uniform, L1-hot
                #pragma unroll
                for (int i = 0; i < 4; i++) {                       // 16 h = 8 pairs
                    ulonglong2 wp2 = wr[i];                         // pairs (4i,4i+1),(4i+2,4i+3)
                    fma2(icp[2*i],     cdd, wp2.x);
                    fma2(icp[2*i + 1], cdd, wp2.y);
                }
            }
        }
        float ic[16];
        {
            const float4* b4 = (const float4*)g_bp;
            #pragma unroll
            for (int i = 0; i < 4; i++) {
                float a0,a1,a2,a3; float4 bv = b4[i];
                unpk(icp[2*i], a0, a1); unpk(icp[2*i+1], a2, a3);
                ic[4*i]=a0+bv.x; ic[4*i+1]=a1+bv.y; ic[4*i+2]=a2+bv.z; ic[4*i+3]=a3+bv.w;
            }
        }

        // ---- 5 greedy steps (everything in registers + shfl) ----
        #pragma unroll
        for (int t = 1; t <= 5; t++) {
            // nic[h] = seq-fma_{k=0..15} ic[k]*Wk[k][h], then +bk
            ull np[8];
            #pragma unroll
            for (int p = 0; p < 8; p++) np[p] = 0ull;
            #pragma unroll
            for (int k = 0; k < 16; k++) {                          // k ascending
                ull a2 = pk2(ic[k], ic[k]);
                const ulonglong2* wr = (const ulonglong2*)(g_wk + k * 16);  // uniform, L1-hot
                #pragma unroll
                for (int i = 0; i < 4; i++) {
                    ulonglong2 wk2 = wr[i];
                    fma2(np[2*i],     a2, wk2.x);
                    fma2(np[2*i + 1], a2, wk2.y);
                }
            }
            float nic[16];
            {
                const float4* b4 = (const float4*)g_bk;
                #pragma unroll
                for (int i = 0; i < 4; i++) {
                    float a0,a1,a2,a3; float4 bv = b4[i];
                    unpk(np[2*i], a0, a1); unpk(np[2*i+1], a2, a3);
                    nic[4*i]=a0+bv.x; nic[4*i+1]=a1+bv.y; nic[4*i+2]=a2+bv.z; nic[4*i+3]=a3+bv.w;
                }
            }

            // score[s] = seq-fma_{h=0..15} nic[h]*src[h]  (in-lane, h ascending)
            float sc = 0.f;
            #pragma unroll
            for (int h = 0; h < 16; h++) sc = fmaf(nic[h], src[h], sc);

            // first-index argmax over the 10 lanes of this group (strict >)
            float bv = -INFINITY; int idx = 0;
            #pragma unroll
            for (int j = 0; j < 10; j++) {
                float v = __shfl_sync(FULL_MASK, sc, grp + j);
                if (v > bv) { bv = v; idx = j; }
            }

            // broadcast selected row; update sum; write output (2 elements per lane)
            const int srcl = grp + idx;
            float* o = g_out + (size_t)b * 96 + (size_t)t * 16;
            #pragma unroll
            for (int h = 0; h < 16; h++) {
                float it = __shfl_sync(FULL_MASK, nic[h], srcl);
                sum[h] += it;                                        // append-order running sum
                if (valid && (h == s || h == s + 10)) o[h] = it;
            }

            // next step's src = mean over t+1 vectors
            if (t == 1) {        // /2 exact
                #pragma unroll
                for (int h = 0; h < 16; h++) src[h] = sum[h] * 0.5f;
            } else if (t == 3) { // /4 exact
                #pragma unroll
                for (int h = 0; h < 16; h++) src[h] = sum[h] * 0.25f;
            } else if (t < 5) {  // /3, /5 IEEE divide
                const float dv = (float)(t + 1);
                #pragma unroll
                for (int h = 0; h < 16; h++) src[h] = __fdiv_rn(sum[h], dv);
            }

            #pragma unroll
            for (int h = 0; h < 16; h++) ic[h] = nic[h];
        }
    }
}

extern "C" void kernel_launch(void* const* d_in, const int* in_sizes, int n_in,
                              void* d_out, int out_size) {
    const float* ui     = (const float*)d_in[0];
    const float* corpus = (const float*)d_in[1];
    const float* wp     = (const float*)d_in[2];
    const float* bp     = (const float*)d_in[3];
    const float* wk     = (const float*)d_in[4];
    const float* bk     = (const float*)d_in[5];
    float* out = (float*)d_out;
    int n_batch = in_sizes[0] / 16;
    // Zero smem; reg-limited to 4 blocks/SM (16 warps). 592 blocks = 4 x 148 SMs.
    attn_greedy_kernel<<<592, 128>>>(ui, corpus, wp, bp, wk, bk, out, n_batch);
}

// round 7
// speedup vs baseline: 1.1486x; 1.1486x over previous
#include <cuda_runtime.h>
#include <math.h>
#include <cstdint>

#define FULL_MASK 0xFFFFFFFFu
typedef unsigned long long ull;

__device__ __forceinline__ ull pk2(float lo, float hi) {
    ull r; asm("mov.b64 %0, {%1, %2};" : "=l"(r) : "f"(lo), "f"(hi)); return r;
}
__device__ __forceinline__ void fma2(ull& d, ull a, ull b) {
    asm("fma.rn.f32x2 %0, %1, %2, %0;" : "+l"(d) : "l"(a), "l"(b));
}
__device__ __forceinline__ void unpk(ull v, float& a, float& b) {
    asm("mov.b64 {%0, %1}, %2;" : "=f"(a), "=f"(b) : "l"(v));
}

// bs=65536, S=10, D=100, H=16, 5 greedy steps.
// s-per-lane: warp handles a TRIPLE of batches; lane = (b3 = l/10, s = l%10).
// Each lane computes ALL 16 h of its row -> corpus value reused 16x in registers.
// Weights live in block-shared smem (broadcast LDS, 1 wf); corpus staged per-warp in
// smem with batch-stride 1032 / row-stride 100 floats => LDS.128 reads are bank-
// conflict-free across all four 8-lane phases (lanes 30/31 shadow (2,8),(2,9) and
// broadcast-merge).
//
// FROZEN numerics contract (bit-matched reference; rel_err 9.309e-8 in R4/R5/R6):
//   - every dot: single-accumulator sequential-k fmaf chain (ascending), bias AFTER
//   - f32x2 pairs two INDEPENDENT h-chains (lo/hi rounded separately)
//   - src = mean(ui): append-order sum; /2,/4 exact mul; /3,/5 via __fdiv_rn
//   - softmax skipped (monotone); first-index argmax via strict >
__global__ __launch_bounds__(96, 5)
void attn_greedy_kernel(const float* __restrict__ g_ui,     // [bs,16]
                        const float* __restrict__ g_corp,   // [bs,10,100]
                        const float* __restrict__ g_wp,     // [100,16]
                        const float* __restrict__ g_bp,     // [16]
                        const float* __restrict__ g_wk,     // [16,16]
                        const float* __restrict__ g_bk,     // [16]
                        float* __restrict__ g_out,          // [bs,6,16]
                        int n_batch)
{
    __shared__ __align__(16) float s_corp[3][3 * 1032];  // per-warp corpus: [b3*1032 + s*100 + d]
    __shared__ __align__(16) float s_wp[100 * 16];       // W_proj row-major [d][h]
    __shared__ __align__(16) float s_wk[16 * 16];        // W_k row-major [k][h]
    __shared__ __align__(16) float s_bp[16];
    __shared__ __align__(16) float s_bk[16];

    const int tid  = threadIdx.x;
    const int w    = tid >> 5;
    const int lane = tid & 31;
    const int l    = (lane < 30) ? lane : (lane - 2);    // lanes 30,31 shadow 28,29 -> broadcast-merge
    const int b3   = l / 10;
    const int s    = l - b3 * 10;
    const int grp  = b3 * 10;
    const bool writer = (lane < 30);

    // ---- stage weights once per block ----
    for (int i = tid; i < 1600; i += 96) s_wp[i] = g_wp[i];
    for (int i = tid; i < 256;  i += 96) s_wk[i] = g_wk[i];
    if (tid < 16) { s_bp[tid] = g_bp[tid]; s_bk[tid] = g_bk[tid]; }
    __syncthreads();

    const int warp_id  = blockIdx.x * 3 + w;
    const int n_warps  = gridDim.x * 3;
    const int n_triple = (n_batch + 2) / 3;
    float* scw = s_corp[w];

    for (int tr = warp_id; tr < n_triple; tr += n_warps) {
        const int  tb    = tr * 3;
        const int  b     = tb + b3;
        const bool valid = writer && (b < n_batch);
        const int  bl    = (b < n_batch) ? b : (n_batch - 1);

        // ---- stage triple corpus: coalesced LDG.128 -> STS.128 (strided layout) ----
        {
            const float4* gsrc = (const float4*)g_corp;
            float4* sc4 = (float4*)scw;
            #pragma unroll
            for (int i = 0; i < 24; i++) {
                int q = lane + 32 * i;
                if (q < 750) {
                    int j = q / 250, rem = q - 250 * j;
                    int bj = tb + j; if (bj >= n_batch) bj = n_batch - 1;
                    sc4[j * 258 + rem] = gsrc[(size_t)bj * 250 + rem];
                }
            }
        }

        // ---- ui: every lane of a group holds the full 16-vector ----
        float sum[16], src[16];
        {
            const float4* u4 = (const float4*)(g_ui + (size_t)bl * 16);
            #pragma unroll
            for (int i = 0; i < 4; i++) {
                float4 v = u4[i];
                sum[4*i]=v.x; sum[4*i+1]=v.y; sum[4*i+2]=v.z; sum[4*i+3]=v.w;
            }
            #pragma unroll
            for (int h = 0; h < 16; h++) src[h] = sum[h];
        }
        if (valid) {
            float* o = g_out + (size_t)b * 96;
            o[s] = sum[s];
            if (s < 6) o[10 + s] = sum[10 + s];
        }
        __syncwarp();                                    // staging visible to all lanes

        // ---- projection: ic[h] = seq-fma_{d=0..99} corp[s,d]*Wp[d,h], then +bp ----
        ull icp[8];
        #pragma unroll
        for (int p = 0; p < 8; p++) icp[p] = 0ull;
        const float* crow = scw + b3 * 1032 + s * 100;   // conflict-free LDS.128 row
        #pragma unroll 5
        for (int c = 0; c < 25; c++) {
            float4 cv = *(const float4*)(crow + 4 * c);  // d = 4c..4c+3
            #pragma unroll
            for (int q = 0; q < 4; q++) {                // d ascending
                float cd = (q == 0) ? cv.x : (q == 1) ? cv.y : (q == 2) ? cv.z : cv.w;
                ull cdd = pk2(cd, cd);
                const ulonglong2* wr = (const ulonglong2*)(s_wp + (4*c + q) * 16);  // broadcast LDS
                #pragma unroll
                for (int i = 0; i < 4; i++) {
                    ulonglong2 wp2 = wr[i];
                    fma2(icp[2*i],     cdd, wp2.x);
                    fma2(icp[2*i + 1], cdd, wp2.y);
                }
            }
        }
        float ic[16];
        {
            const float4* b4 = (const float4*)s_bp;
            #pragma unroll
            for (int i = 0; i < 4; i++) {
                float a0,a1,a2,a3; float4 bv = b4[i];
                unpk(icp[2*i], a0, a1); unpk(icp[2*i+1], a2, a3);
                ic[4*i]=a0+bv.x; ic[4*i+1]=a1+bv.y; ic[4*i+2]=a2+bv.z; ic[4*i+3]=a3+bv.w;
            }
        }

        // ---- 5 greedy steps (registers + shfl) ----
        #pragma unroll
        for (int t = 1; t <= 5; t++) {
            // nic[h] = seq-fma_{k=0..15} ic[k]*Wk[k][h], then +bk
            ull np[8];
            #pragma unroll
            for (int p = 0; p < 8; p++) np[p] = 0ull;
            #pragma unroll
            for (int k = 0; k < 16; k++) {               // k ascending
                ull a2 = pk2(ic[k], ic[k]);
                const ulonglong2* wr = (const ulonglong2*)(s_wk + k * 16);  // broadcast LDS
                #pragma unroll
                for (int i = 0; i < 4; i++) {
                    ulonglong2 wk2 = wr[i];
                    fma2(np[2*i],     a2, wk2.x);
                    fma2(np[2*i + 1], a2, wk2.y);
                }
            }
            float nic[16];
            {
                const float4* b4 = (const float4*)s_bk;
                #pragma unroll
                for (int i = 0; i < 4; i++) {
                    float a0,a1,a2,a3; float4 bv = b4[i];
                    unpk(np[2*i], a0, a1); unpk(np[2*i+1], a2, a3);
                    nic[4*i]=a0+bv.x; nic[4*i+1]=a1+bv.y; nic[4*i+2]=a2+bv.z; nic[4*i+3]=a3+bv.w;
                }
            }

            // score = seq-fma_{h=0..15} nic[h]*src[h]  (in-lane, h ascending)
            float sc = 0.f;
            #pragma unroll
            for (int h = 0; h < 16; h++) sc = fmaf(nic[h], src[h], sc);

            // first-index argmax over the 10 lanes of this group (strict >)
            float bv = -INFINITY; int idx = 0;
            #pragma unroll
            for (int j = 0; j < 10; j++) {
                float v = __shfl_sync(FULL_MASK, sc, grp + j);
                if (v > bv) { bv = v; idx = j; }
            }

            // broadcast selected row; update sum; write output
            const int srcl = grp + idx;
            float* o = g_out + (size_t)b * 96 + (size_t)t * 16;
            #pragma unroll
            for (int h = 0; h < 16; h++) {
                float it = __shfl_sync(FULL_MASK, nic[h], srcl);
                sum[h] += it;                            // append-order running sum
                if (valid && (h == s || h == s + 10)) o[h] = it;
            }

            // next step's src = mean over t+1 vectors
            if (t == 1) {
                #pragma unroll
                for (int h = 0; h < 16; h++) src[h] = sum[h] * 0.5f;
            } else if (t == 3) {
                #pragma unroll
                for (int h = 0; h < 16; h++) src[h] = sum[h] * 0.25f;
            } else if (t < 5) {
                const float dv = (float)(t + 1);
                #pragma unroll
                for (int h = 0; h < 16; h++) src[h] = __fdiv_rn(sum[h], dv);
            }

            #pragma unroll
            for (int h = 0; h < 16; h++) ic[h] = nic[h];
        }
        __syncwarp();                                    // all corpus reads done before restage
    }
}

extern "C" void kernel_launch(void* const* d_in, const int* in_sizes, int n_in,
                              void* d_out, int out_size) {
    const float* ui     = (const float*)d_in[0];
    const float* corpus = (const float*)d_in[1];
    const float* wp     = (const float*)d_in[2];
    const float* bp     = (const float*)d_in[3];
    const float* wk     = (const float*)d_in[4];
    const float* bk     = (const float*)d_in[5];
    float* out = (float*)d_out;
    int n_batch = in_sizes[0] / 16;
    // 96-thread blocks, 44.7KB static smem -> 5 blocks/SM (15 warps). 740 = 5 x 148.
    attn_greedy_kernel<<<740, 96>>>(ui, corpus, wp, bp, wk, bk, out, n_batch);
}